// round 1
// baseline (speedup 1.0000x reference)
#include <cuda_runtime.h>
#include <math.h>

#define Bn 4
#define Nn 2048
#define IND 128
#define Hn 4
#define Dn 64
#define C 256   // H*D
#define ROWS (Bn*Nn)   // 8192

// ---- scratch (static device globals; no allocation) ----
__device__ float g_Wh[ROWS*C];        // [B*N, 256]
__device__ float g_src[Bn*Hn*Nn];     // [B,H,N]
__device__ float g_dst[Bn*Hn*Nn];
__device__ float g_hnew[ROWS*C];
__device__ float g_psum[128*C];
__device__ float g_psq[128*C];
__device__ float g_mean[C];
__device__ float g_rstd[C];

// ============================================================
// K1: Wh = h @ W   (8192 x 256 x 128)
// 32 rows per block, 256 threads (one output column each).
// ============================================================
__global__ __launch_bounds__(256) void k_gemm(const float* __restrict__ hIn,
                                              const float* __restrict__ W) {
    __shared__ float hs[32 * IND];
    int row0 = blockIdx.x * 32;
    const float4* gp = (const float4*)(hIn + (size_t)row0 * IND);
    float4* sp = (float4*)hs;
    for (int i = threadIdx.x; i < 32 * IND / 4; i += 256) sp[i] = gp[i];
    __syncthreads();

    int c = threadIdx.x;
    float acc[32];
#pragma unroll
    for (int r = 0; r < 32; r++) acc[r] = 0.f;

    for (int k = 0; k < IND; k += 4) {
        float w0 = __ldg(&W[(k + 0) * C + c]);
        float w1 = __ldg(&W[(k + 1) * C + c]);
        float w2 = __ldg(&W[(k + 2) * C + c]);
        float w3 = __ldg(&W[(k + 3) * C + c]);
#pragma unroll
        for (int r = 0; r < 32; r++) {
            float4 hv = *(const float4*)&hs[r * IND + k];
            acc[r] += hv.x * w0 + hv.y * w1 + hv.z * w2 + hv.w * w3;
        }
    }
#pragma unroll
    for (int r = 0; r < 32; r++) g_Wh[(size_t)(row0 + r) * C + c] = acc[r];
}

// ============================================================
// K2: src[b,h,n] = Wh[b,h,n,:].a[h,:D] ; dst likewise with a[h,D:]
// One warp per (b,n,h).
// ============================================================
__global__ __launch_bounds__(256) void k_srcdst(const float* __restrict__ a) {
    int gw = blockIdx.x * 8 + (threadIdx.x >> 5);
    int lane = threadIdx.x & 31;
    int hh = gw & 3;
    int n  = (gw >> 2) & (Nn - 1);
    int b  = gw >> 13;
    const float2 v  = ((const float2*)(g_Wh + (size_t)(b * Nn + n) * C + hh * Dn))[lane];
    const float2 a1 = ((const float2*)(a + hh * 2 * Dn))[lane];
    const float2 a2 = ((const float2*)(a + hh * 2 * Dn + Dn))[lane];
    float s = v.x * a1.x + v.y * a1.y;
    float d = v.x * a2.x + v.y * a2.y;
#pragma unroll
    for (int o = 16; o > 0; o >>= 1) {
        s += __shfl_xor_sync(0xffffffffu, s, o);
        d += __shfl_xor_sync(0xffffffffu, d, o);
    }
    if (lane == 0) {
        g_src[(b * Hn + hh) * Nn + n] = s;
        g_dst[(b * Hn + hh) * Nn + n] = d;
    }
}

// ============================================================
// K3: attention. Block = (b, h, i-tile of 64). TJ = 64.
// Phase A: P[i][j] = adj ? exp(leaky(src_i + dst_j)) : 0  (smem)
// Phase B: register-blocked PV accumulate (2 i x 8 d per thread)
// No max subtraction (scores ~N(0,1); exp range safe in fp32).
// ============================================================
__global__ __launch_bounds__(256) void k_attn(const int* __restrict__ adj) {
    __shared__ float Wh_s[64 * 68];
    __shared__ float P_s [64 * 68];
    __shared__ float dst_s[64];
    __shared__ float rowsum_s[64];

    int b  = blockIdx.z, hh = blockIdx.y;
    int i0 = blockIdx.x * 64;
    int t  = threadIdx.x;

    // phase A mapping: 4 threads per i-row, 16 j each
    int ia = t >> 2, jq = t & 3;
    // phase B mapping: rows {iq, iq+32}, cols {4q..4q+3, 32+4q..32+4q+3}
    int iq = t >> 3, q = t & 7;

    float src_i = g_src[(b * Hn + hh) * Nn + i0 + ia];
    float rs = 0.f;
    float acc[16];
#pragma unroll
    for (int r = 0; r < 16; r++) acc[r] = 0.f;

    const float* Whb = g_Wh + (size_t)(b * Nn) * C + hh * Dn;
    const float* db  = g_dst + (b * Hn + hh) * Nn;
    int jr = t >> 2, c4 = t & 3;

    for (int j0 = 0; j0 < Nn; j0 += 64) {
        // load Wh tile [64 j][64 d] (row stride 68 floats, padded)
        {
            const float4* gp = (const float4*)(Whb + (size_t)(j0 + jr) * C);
            float4* sp = (float4*)&Wh_s[jr * 68];
#pragma unroll
            for (int u = 0; u < 4; u++) sp[c4 * 4 + u] = gp[c4 * 4 + u];
        }
        if (t < 64) dst_s[t] = db[j0 + t];
        __syncthreads();

        // ---- phase A: scores ----
        const int4* ap = (const int4*)(adj + (size_t)(i0 + ia) * Nn + j0 + jq * 16);
        float part = 0.f;
#pragma unroll
        for (int g4 = 0; g4 < 4; g4++) {
            int4 av = ap[g4];
            float4 wv;
            float e0 = src_i + dst_s[jq * 16 + 4 * g4 + 0];
            float e1 = src_i + dst_s[jq * 16 + 4 * g4 + 1];
            float e2 = src_i + dst_s[jq * 16 + 4 * g4 + 2];
            float e3 = src_i + dst_s[jq * 16 + 4 * g4 + 3];
            e0 = e0 >= 0.f ? e0 : 0.2f * e0;
            e1 = e1 >= 0.f ? e1 : 0.2f * e1;
            e2 = e2 >= 0.f ? e2 : 0.2f * e2;
            e3 = e3 >= 0.f ? e3 : 0.2f * e3;
            wv.x = av.x ? __expf(e0) : 0.f;
            wv.y = av.y ? __expf(e1) : 0.f;
            wv.z = av.z ? __expf(e2) : 0.f;
            wv.w = av.w ? __expf(e3) : 0.f;
            *(float4*)&P_s[ia * 68 + jq * 16 + 4 * g4] = wv;
            part += wv.x + wv.y + wv.z + wv.w;
        }
        rs += part;
        __syncthreads();

        // ---- phase B: PV accumulate ----
#pragma unroll 8
        for (int jj = 0; jj < 64; jj++) {
            float p0 = P_s[iq * 68 + jj];
            float p1 = P_s[(iq + 32) * 68 + jj];
            float4 w0 = *(const float4*)&Wh_s[jj * 68 + 4 * q];
            float4 w1 = *(const float4*)&Wh_s[jj * 68 + 32 + 4 * q];
            acc[0]  += p0 * w0.x; acc[1]  += p0 * w0.y; acc[2]  += p0 * w0.z; acc[3]  += p0 * w0.w;
            acc[4]  += p0 * w1.x; acc[5]  += p0 * w1.y; acc[6]  += p0 * w1.z; acc[7]  += p0 * w1.w;
            acc[8]  += p1 * w0.x; acc[9]  += p1 * w0.y; acc[10] += p1 * w0.z; acc[11] += p1 * w0.w;
            acc[12] += p1 * w1.x; acc[13] += p1 * w1.y; acc[14] += p1 * w1.z; acc[15] += p1 * w1.w;
        }
        __syncthreads();
    }

    // rowsum reduce across the 4 jq lanes (consecutive lanes)
    rs += __shfl_down_sync(0xffffffffu, rs, 2);
    rs += __shfl_down_sync(0xffffffffu, rs, 1);
    if (jq == 0) rowsum_s[ia] = rs;
    __syncthreads();

    float r0 = rowsum_s[iq];      float inv0 = r0 > 0.f ? 1.f / r0 : 0.f;
    float r1 = rowsum_s[iq + 32]; float inv1 = r1 > 0.f ? 1.f / r1 : 0.f;

    float* o0 = g_hnew + (size_t)(b * Nn + i0 + iq) * C + hh * Dn;
    float* o1 = g_hnew + (size_t)(b * Nn + i0 + iq + 32) * C + hh * Dn;
    *(float4*)&o0[4 * q]      = make_float4(acc[0] * inv0,  acc[1] * inv0,  acc[2] * inv0,  acc[3] * inv0);
    *(float4*)&o0[32 + 4 * q] = make_float4(acc[4] * inv0,  acc[5] * inv0,  acc[6] * inv0,  acc[7] * inv0);
    *(float4*)&o1[4 * q]      = make_float4(acc[8] * inv1,  acc[9] * inv1,  acc[10] * inv1, acc[11] * inv1);
    *(float4*)&o1[32 + 4 * q] = make_float4(acc[12] * inv1, acc[13] * inv1, acc[14] * inv1, acc[15] * inv1);
}

// ============================================================
// K4/K5: BatchNorm stats (deterministic two-stage, no atomics)
// ============================================================
__global__ __launch_bounds__(256) void k_bn_partial() {
    int c = threadIdx.x;
    int r0 = blockIdx.x * 64;
    float s = 0.f, ss = 0.f;
    for (int r = 0; r < 64; r++) {
        float x = g_hnew[(size_t)(r0 + r) * C + c];
        s += x; ss += x * x;
    }
    g_psum[blockIdx.x * C + c] = s;
    g_psq [blockIdx.x * C + c] = ss;
}

__global__ __launch_bounds__(256) void k_bn_final() {
    int c = threadIdx.x;
    float s = 0.f, ss = 0.f;
    for (int k = 0; k < 128; k++) {
        s  += g_psum[k * C + c];
        ss += g_psq [k * C + c];
    }
    float m = s * (1.f / (float)ROWS);
    float v = ss * (1.f / (float)ROWS) - m * m;
    v = v > 0.f ? v : 0.f;
    g_mean[c] = m;
    g_rstd[c] = rsqrtf(v + 1e-5f);
}

// ============================================================
// K6: normalize + affine + ELU
// ============================================================
__global__ __launch_bounds__(256) void k_norm(const float* __restrict__ gamma,
                                              const float* __restrict__ beta,
                                              float* __restrict__ out) {
    int idx = blockIdx.x * 256 + threadIdx.x;   // float4 index
    int c = (idx & 63) * 4;                     // channel of .x
    float4 x = ((const float4*)g_hnew)[idx];
    float4 y;
    y.x = (x.x - g_mean[c + 0]) * g_rstd[c + 0] * gamma[c + 0] + beta[c + 0];
    y.y = (x.y - g_mean[c + 1]) * g_rstd[c + 1] * gamma[c + 1] + beta[c + 1];
    y.z = (x.z - g_mean[c + 2]) * g_rstd[c + 2] * gamma[c + 2] + beta[c + 2];
    y.w = (x.w - g_mean[c + 3]) * g_rstd[c + 3] * gamma[c + 3] + beta[c + 3];
    y.x = y.x > 0.f ? y.x : expm1f(y.x);
    y.y = y.y > 0.f ? y.y : expm1f(y.y);
    y.z = y.z > 0.f ? y.z : expm1f(y.z);
    y.w = y.w > 0.f ? y.w : expm1f(y.w);
    ((float4*)out)[idx] = y;
}

// ============================================================
extern "C" void kernel_launch(void* const* d_in, const int* in_sizes, int n_in,
                              void* d_out, int out_size) {
    const float* h     = (const float*)d_in[0];
    const float* W     = (const float*)d_in[1];
    const float* a     = (const float*)d_in[2];
    const float* gamma = (const float*)d_in[3];
    const float* beta  = (const float*)d_in[4];
    const int*   adj   = (const int*)d_in[5];
    float* out = (float*)d_out;

    k_gemm<<<ROWS / 32, 256>>>(h, W);
    k_srcdst<<<Bn * Nn * Hn / 8, 256>>>(a);
    dim3 g(Nn / 64, Hn, Bn);
    k_attn<<<g, 256>>>(adj);
    k_bn_partial<<<128, 256>>>();
    k_bn_final<<<1, 256>>>();
    k_norm<<<ROWS * C / 4 / 256, 256>>>(gamma, beta, out);
}

// round 2
// speedup vs baseline: 1.0062x; 1.0062x over previous
#include <cuda_runtime.h>
#include <math.h>

#define Bn 4
#define Nn 2048
#define IND 128
#define Hn 4
#define Dn 64
#define C 256   // H*D
#define ROWS (Bn*Nn)   // 8192

// ---- scratch (static device globals; no allocation) ----
__device__ float g_Wh[ROWS*C];        // [B*N, 256]
__device__ float g_src[Bn*Hn*Nn];     // [B,H,N]
__device__ float g_dst[Bn*Hn*Nn];
__device__ float g_hnew[ROWS*C];
__device__ float g_psum[128*C];
__device__ float g_psq[128*C];
__device__ float g_mean[C];
__device__ float g_rstd[C];

// ---- packed f32x2 helpers (Blackwell FFMA2 pipe, PTX-only) ----
__device__ __forceinline__ unsigned long long pack2(float x) {
    unsigned long long r;
    asm("mov.b64 %0, {%1, %1};" : "=l"(r) : "f"(x));
    return r;
}
__device__ __forceinline__ void ffma2(unsigned long long& d,
                                      unsigned long long a,
                                      unsigned long long b) {
    asm("fma.rn.f32x2 %0, %1, %2, %0;" : "+l"(d) : "l"(a), "l"(b));
}
__device__ __forceinline__ float2 unpack2(unsigned long long v) {
    float2 r;
    asm("mov.b64 {%0, %1}, %2;" : "=f"(r.x), "=f"(r.y) : "l"(v));
    return r;
}

// ============================================================
// K1: Wh = h @ W   (8192 x 256 x 128)
// ============================================================
__global__ __launch_bounds__(256) void k_gemm(const float* __restrict__ hIn,
                                              const float* __restrict__ W) {
    __shared__ float hs[32 * IND];
    int row0 = blockIdx.x * 32;
    const float4* gp = (const float4*)(hIn + (size_t)row0 * IND);
    float4* sp = (float4*)hs;
    for (int i = threadIdx.x; i < 32 * IND / 4; i += 256) sp[i] = gp[i];
    __syncthreads();

    int c = threadIdx.x;
    float acc[32];
#pragma unroll
    for (int r = 0; r < 32; r++) acc[r] = 0.f;

    for (int k = 0; k < IND; k += 4) {
        float w0 = __ldg(&W[(k + 0) * C + c]);
        float w1 = __ldg(&W[(k + 1) * C + c]);
        float w2 = __ldg(&W[(k + 2) * C + c]);
        float w3 = __ldg(&W[(k + 3) * C + c]);
#pragma unroll
        for (int r = 0; r < 32; r++) {
            float4 hv = *(const float4*)&hs[r * IND + k];
            acc[r] += hv.x * w0 + hv.y * w1 + hv.z * w2 + hv.w * w3;
        }
    }
#pragma unroll
    for (int r = 0; r < 32; r++) g_Wh[(size_t)(row0 + r) * C + c] = acc[r];
}

// ============================================================
// K2: src/dst projections. One warp per (b,n,h).
// ============================================================
__global__ __launch_bounds__(256) void k_srcdst(const float* __restrict__ a) {
    int gw = blockIdx.x * 8 + (threadIdx.x >> 5);
    int lane = threadIdx.x & 31;
    int hh = gw & 3;
    int n  = (gw >> 2) & (Nn - 1);
    int b  = gw >> 13;
    const float2 v  = ((const float2*)(g_Wh + (size_t)(b * Nn + n) * C + hh * Dn))[lane];
    const float2 a1 = ((const float2*)(a + hh * 2 * Dn))[lane];
    const float2 a2 = ((const float2*)(a + hh * 2 * Dn + Dn))[lane];
    float s = v.x * a1.x + v.y * a1.y;
    float d = v.x * a2.x + v.y * a2.y;
#pragma unroll
    for (int o = 16; o > 0; o >>= 1) {
        s += __shfl_xor_sync(0xffffffffu, s, o);
        d += __shfl_xor_sync(0xffffffffu, d, o);
    }
    if (lane == 0) {
        g_src[(b * Hn + hh) * Nn + n] = s;
        g_dst[(b * Hn + hh) * Nn + n] = d;
    }
}

// ============================================================
// K3: attention. Block = (b, h, i-tile of 64). TJ = 64.
// Phase A: P[i][j] = adj ? exp(leaky(src_i + dst_j)) : 0  (smem)
// Phase B: register-blocked PV with packed fma.rn.f32x2
// ============================================================
__global__ __launch_bounds__(256) void k_attn(const int* __restrict__ adj) {
    __shared__ float Wh_s[64 * 68];
    __shared__ float P_s [64 * 68];
    __shared__ float dst_s[64];
    __shared__ float rowsum_s[64];

    int b  = blockIdx.z, hh = blockIdx.y;
    int i0 = blockIdx.x * 64;
    int t  = threadIdx.x;

    int ia = t >> 2, jq = t & 3;       // phase A: 4 threads per i-row
    int iq = t >> 3, q = t & 7;        // phase B: rows {iq, iq+32}, d {4q.., 32+4q..}

    float src_i = g_src[(b * Hn + hh) * Nn + i0 + ia];
    float rs = 0.f;
    unsigned long long acc[8];
#pragma unroll
    for (int r = 0; r < 8; r++) acc[r] = 0ull;

    const float* Whb = g_Wh + (size_t)(b * Nn) * C + hh * Dn;
    const float* db  = g_dst + (b * Hn + hh) * Nn;
    int jr = t >> 2, c4 = t & 3;

    for (int j0 = 0; j0 < Nn; j0 += 64) {
        // load Wh tile [64 j][64 d] (row stride 68 floats, padded)
        {
            const float4* gp = (const float4*)(Whb + (size_t)(j0 + jr) * C);
            float4* sp = (float4*)&Wh_s[jr * 68];
#pragma unroll
            for (int u = 0; u < 4; u++) sp[c4 * 4 + u] = gp[c4 * 4 + u];
        }
        if (t < 64) dst_s[t] = db[j0 + t];
        __syncthreads();

        // ---- phase A: scores ----
        const int4* ap = (const int4*)(adj + (size_t)(i0 + ia) * Nn + j0 + jq * 16);
        float part = 0.f;
#pragma unroll
        for (int g4 = 0; g4 < 4; g4++) {
            int4 av = ap[g4];
            float4 wv;
            float e0 = src_i + dst_s[jq * 16 + 4 * g4 + 0];
            float e1 = src_i + dst_s[jq * 16 + 4 * g4 + 1];
            float e2 = src_i + dst_s[jq * 16 + 4 * g4 + 2];
            float e3 = src_i + dst_s[jq * 16 + 4 * g4 + 3];
            e0 = e0 >= 0.f ? e0 : 0.2f * e0;
            e1 = e1 >= 0.f ? e1 : 0.2f * e1;
            e2 = e2 >= 0.f ? e2 : 0.2f * e2;
            e3 = e3 >= 0.f ? e3 : 0.2f * e3;
            wv.x = av.x ? __expf(e0) : 0.f;
            wv.y = av.y ? __expf(e1) : 0.f;
            wv.z = av.z ? __expf(e2) : 0.f;
            wv.w = av.w ? __expf(e3) : 0.f;
            *(float4*)&P_s[ia * 68 + jq * 16 + 4 * g4] = wv;
            part += wv.x + wv.y + wv.z + wv.w;
        }
        rs += part;
        __syncthreads();

        // ---- phase B: packed-f32x2 PV accumulate ----
#pragma unroll 8
        for (int jj = 0; jj < 64; jj++) {
            float p0 = P_s[iq * 68 + jj];
            float p1 = P_s[(iq + 32) * 68 + jj];
            unsigned long long pp0 = pack2(p0);
            unsigned long long pp1 = pack2(p1);
            ulonglong2 w0 = *(const ulonglong2*)&Wh_s[jj * 68 + 4 * q];
            ulonglong2 w1 = *(const ulonglong2*)&Wh_s[jj * 68 + 32 + 4 * q];
            ffma2(acc[0], pp0, w0.x); ffma2(acc[1], pp0, w0.y);
            ffma2(acc[2], pp0, w1.x); ffma2(acc[3], pp0, w1.y);
            ffma2(acc[4], pp1, w0.x); ffma2(acc[5], pp1, w0.y);
            ffma2(acc[6], pp1, w1.x); ffma2(acc[7], pp1, w1.y);
        }
        __syncthreads();
    }

    // rowsum reduce across the 4 jq lanes (consecutive lanes)
    rs += __shfl_down_sync(0xffffffffu, rs, 2);
    rs += __shfl_down_sync(0xffffffffu, rs, 1);
    if (jq == 0) rowsum_s[ia] = rs;
    __syncthreads();

    float r0 = rowsum_s[iq];      float inv0 = r0 > 0.f ? 1.f / r0 : 0.f;
    float r1 = rowsum_s[iq + 32]; float inv1 = r1 > 0.f ? 1.f / r1 : 0.f;

    float2 a0 = unpack2(acc[0]), a1 = unpack2(acc[1]);
    float2 a2 = unpack2(acc[2]), a3 = unpack2(acc[3]);
    float2 a4 = unpack2(acc[4]), a5 = unpack2(acc[5]);
    float2 a6 = unpack2(acc[6]), a7 = unpack2(acc[7]);

    float* o0 = g_hnew + (size_t)(b * Nn + i0 + iq) * C + hh * Dn;
    float* o1 = g_hnew + (size_t)(b * Nn + i0 + iq + 32) * C + hh * Dn;
    *(float4*)&o0[4 * q]      = make_float4(a0.x * inv0, a0.y * inv0, a1.x * inv0, a1.y * inv0);
    *(float4*)&o0[32 + 4 * q] = make_float4(a2.x * inv0, a2.y * inv0, a3.x * inv0, a3.y * inv0);
    *(float4*)&o1[4 * q]      = make_float4(a4.x * inv1, a4.y * inv1, a5.x * inv1, a5.y * inv1);
    *(float4*)&o1[32 + 4 * q] = make_float4(a6.x * inv1, a6.y * inv1, a7.x * inv1, a7.y * inv1);
}

// ============================================================
// K4/K5: BatchNorm stats (deterministic two-stage)
// ============================================================
__global__ __launch_bounds__(256) void k_bn_partial() {
    int c = threadIdx.x;
    int r0 = blockIdx.x * 64;
    float s = 0.f, ss = 0.f;
    for (int r = 0; r < 64; r++) {
        float x = g_hnew[(size_t)(r0 + r) * C + c];
        s += x; ss += x * x;
    }
    g_psum[blockIdx.x * C + c] = s;
    g_psq [blockIdx.x * C + c] = ss;
}

__global__ __launch_bounds__(256) void k_bn_final() {
    int c = threadIdx.x;
    float s = 0.f, ss = 0.f;
    for (int k = 0; k < 128; k++) {
        s  += g_psum[k * C + c];
        ss += g_psq [k * C + c];
    }
    float m = s * (1.f / (float)ROWS);
    float v = ss * (1.f / (float)ROWS) - m * m;
    v = v > 0.f ? v : 0.f;
    g_mean[c] = m;
    g_rstd[c] = rsqrtf(v + 1e-5f);
}

// ============================================================
// K6: normalize + affine + ELU
// ============================================================
__global__ __launch_bounds__(256) void k_norm(const float* __restrict__ gamma,
                                              const float* __restrict__ beta,
                                              float* __restrict__ out) {
    int idx = blockIdx.x * 256 + threadIdx.x;   // float4 index
    int c = (idx & 63) * 4;                     // channel of .x
    float4 x = ((const float4*)g_hnew)[idx];
    float4 y;
    y.x = (x.x - g_mean[c + 0]) * g_rstd[c + 0] * gamma[c + 0] + beta[c + 0];
    y.y = (x.y - g_mean[c + 1]) * g_rstd[c + 1] * gamma[c + 1] + beta[c + 1];
    y.z = (x.z - g_mean[c + 2]) * g_rstd[c + 2] * gamma[c + 2] + beta[c + 2];
    y.w = (x.w - g_mean[c + 3]) * g_rstd[c + 3] * gamma[c + 3] + beta[c + 3];
    y.x = y.x > 0.f ? y.x : expm1f(y.x);
    y.y = y.y > 0.f ? y.y : expm1f(y.y);
    y.z = y.z > 0.f ? y.z : expm1f(y.z);
    y.w = y.w > 0.f ? y.w : expm1f(y.w);
    ((float4*)out)[idx] = y;
}

// ============================================================
extern "C" void kernel_launch(void* const* d_in, const int* in_sizes, int n_in,
                              void* d_out, int out_size) {
    const float* h     = (const float*)d_in[0];
    const float* W     = (const float*)d_in[1];
    const float* a     = (const float*)d_in[2];
    const float* gamma = (const float*)d_in[3];
    const float* beta  = (const float*)d_in[4];
    const int*   adj   = (const int*)d_in[5];
    float* out = (float*)d_out;

    k_gemm<<<ROWS / 32, 256>>>(h, W);
    k_srcdst<<<Bn * Nn * Hn / 8, 256>>>(a);
    dim3 g(Nn / 64, Hn, Bn);
    k_attn<<<g, 256>>>(adj);
    k_bn_partial<<<128, 256>>>();
    k_bn_final<<<1, 256>>>();
    k_norm<<<ROWS * C / 4 / 256, 256>>>(gamma, beta, out);
}

// round 3
// speedup vs baseline: 1.7919x; 1.7809x over previous
#include <cuda_runtime.h>
#include <math.h>

#define Bn 4
#define Nn 2048
#define IND 128
#define Hn 4
#define Dn 64
#define C 256   // H*D
#define ROWS (Bn*Nn)   // 8192

// ---- scratch (static device globals; no allocation) ----
__device__ float g_Wh[ROWS*C];        // [B*N, 256]
__device__ float g_src[Bn*Hn*Nn];     // [B,H,N]
__device__ float g_dst[Bn*Hn*Nn];
__device__ float g_hnew[ROWS*C];
__device__ float g_psum[128*C];
__device__ float g_psq[128*C];
__device__ float g_mean[C];
__device__ float g_rstd[C];

// ---- tf32 helpers ----
__device__ __forceinline__ unsigned int f2tf32(float x) {
    unsigned int r;
    asm("cvt.rna.tf32.f32 %0, %1;" : "=r"(r) : "f"(x));
    return r;
}
__device__ __forceinline__ void mma_tf32(float* c,
                                         unsigned int a0, unsigned int a1,
                                         unsigned int a2, unsigned int a3,
                                         unsigned int b0, unsigned int b1) {
    asm("mma.sync.aligned.m16n8k8.row.col.f32.tf32.tf32.f32 "
        "{%0,%1,%2,%3}, {%4,%5,%6,%7}, {%8,%9}, {%0,%1,%2,%3};"
        : "+f"(c[0]), "+f"(c[1]), "+f"(c[2]), "+f"(c[3])
        : "r"(a0), "r"(a1), "r"(a2), "r"(a3), "r"(b0), "r"(b1));
}

// ============================================================
// K1: Wh = h @ W   (8192 x 256 x 128)
// ============================================================
__global__ __launch_bounds__(256) void k_gemm(const float* __restrict__ hIn,
                                              const float* __restrict__ W) {
    __shared__ float hs[32 * IND];
    int row0 = blockIdx.x * 32;
    const float4* gp = (const float4*)(hIn + (size_t)row0 * IND);
    float4* sp = (float4*)hs;
    for (int i = threadIdx.x; i < 32 * IND / 4; i += 256) sp[i] = gp[i];
    __syncthreads();

    int c = threadIdx.x;
    float acc[32];
#pragma unroll
    for (int r = 0; r < 32; r++) acc[r] = 0.f;

    for (int k = 0; k < IND; k += 4) {
        float w0 = __ldg(&W[(k + 0) * C + c]);
        float w1 = __ldg(&W[(k + 1) * C + c]);
        float w2 = __ldg(&W[(k + 2) * C + c]);
        float w3 = __ldg(&W[(k + 3) * C + c]);
#pragma unroll
        for (int r = 0; r < 32; r++) {
            float4 hv = *(const float4*)&hs[r * IND + k];
            acc[r] += hv.x * w0 + hv.y * w1 + hv.z * w2 + hv.w * w3;
        }
    }
#pragma unroll
    for (int r = 0; r < 32; r++) g_Wh[(size_t)(row0 + r) * C + c] = acc[r];
}

// ============================================================
// K2: src/dst projections. One warp per (b,n,h).
// ============================================================
__global__ __launch_bounds__(256) void k_srcdst(const float* __restrict__ a) {
    int gw = blockIdx.x * 8 + (threadIdx.x >> 5);
    int lane = threadIdx.x & 31;
    int hh = gw & 3;
    int n  = (gw >> 2) & (Nn - 1);
    int b  = gw >> 13;
    const float2 v  = ((const float2*)(g_Wh + (size_t)(b * Nn + n) * C + hh * Dn))[lane];
    const float2 a1 = ((const float2*)(a + hh * 2 * Dn))[lane];
    const float2 a2 = ((const float2*)(a + hh * 2 * Dn + Dn))[lane];
    float s = v.x * a1.x + v.y * a1.y;
    float d = v.x * a2.x + v.y * a2.y;
#pragma unroll
    for (int o = 16; o > 0; o >>= 1) {
        s += __shfl_xor_sync(0xffffffffu, s, o);
        d += __shfl_xor_sync(0xffffffffu, d, o);
    }
    if (lane == 0) {
        g_src[(b * Hn + hh) * Nn + n] = s;
        g_dst[(b * Hn + hh) * Nn + n] = d;
    }
}

// ============================================================
// K3: attention. Block = (b, h, i-tile of 64). TJ = 64.
// Phase A: P[i][j] = adj ? exp(leaky(src_i + dst_j)) : 0, stored as tf32
// Phase B: tensor-core PV: 8 warps, each 16i x 32d, mma.m16n8k8 tf32
// ============================================================
__global__ __launch_bounds__(256) void k_attn(const int* __restrict__ adj, int tile_off) {
    __shared__ unsigned int Wh_s[64 * 68];   // tf32-rounded Wh tile [j][d]
    __shared__ unsigned int P_s [64 * 68];   // tf32-rounded P tile  [i][j]
    __shared__ float dst_s[64];
    __shared__ float rowsum_s[64];

    int b  = blockIdx.z, hh = blockIdx.y;
    int i0 = (blockIdx.x + tile_off) * 64;
    int t  = threadIdx.x;

    int ia = t >> 2, jq = t & 3;          // phase A: 4 threads per i-row
    int w  = t >> 5, lane = t & 31;       // phase B warp mapping
    int wi = w >> 1, wd = w & 1;          // 16-row i-block, 32-col d-half
    int gid = lane >> 2, tig = lane & 3;

    float src_i = g_src[(b * Hn + hh) * Nn + i0 + ia];
    float rs = 0.f;
    float acc[4][4];
#pragma unroll
    for (int n = 0; n < 4; n++)
#pragma unroll
        for (int r = 0; r < 4; r++) acc[n][r] = 0.f;

    const float* Whb = g_Wh + (size_t)(b * Nn) * C + hh * Dn;
    const float* db  = g_dst + (b * Hn + hh) * Nn;
    int jr = t >> 2, c4 = t & 3;

    for (int j0 = 0; j0 < Nn; j0 += 64) {
        // load Wh tile [64 j][64 d], tf32-rounded (row stride 68, padded)
        {
            const float4* gp = (const float4*)(Whb + (size_t)(j0 + jr) * C);
            unsigned int* sp = &Wh_s[jr * 68];
#pragma unroll
            for (int u = 0; u < 4; u++) {
                float4 v = gp[c4 * 4 + u];
                sp[c4 * 16 + 4 * u + 0] = f2tf32(v.x);
                sp[c4 * 16 + 4 * u + 1] = f2tf32(v.y);
                sp[c4 * 16 + 4 * u + 2] = f2tf32(v.z);
                sp[c4 * 16 + 4 * u + 3] = f2tf32(v.w);
            }
        }
        if (t < 64) dst_s[t] = db[j0 + t];
        __syncthreads();

        // ---- phase A: scores (tf32-rounded into P_s) ----
        const int4* ap = (const int4*)(adj + (size_t)(i0 + ia) * Nn + j0 + jq * 16);
        float part = 0.f;
#pragma unroll
        for (int g4 = 0; g4 < 4; g4++) {
            int4 av = ap[g4];
            float e0 = src_i + dst_s[jq * 16 + 4 * g4 + 0];
            float e1 = src_i + dst_s[jq * 16 + 4 * g4 + 1];
            float e2 = src_i + dst_s[jq * 16 + 4 * g4 + 2];
            float e3 = src_i + dst_s[jq * 16 + 4 * g4 + 3];
            e0 = fmaxf(e0, 0.2f * e0);
            e1 = fmaxf(e1, 0.2f * e1);
            e2 = fmaxf(e2, 0.2f * e2);
            e3 = fmaxf(e3, 0.2f * e3);
            float w0 = av.x ? __expf(e0) : 0.f;
            float w1 = av.y ? __expf(e1) : 0.f;
            float w2 = av.z ? __expf(e2) : 0.f;
            float w3 = av.w ? __expf(e3) : 0.f;
            uint4 pv;
            pv.x = f2tf32(w0); pv.y = f2tf32(w1);
            pv.z = f2tf32(w2); pv.w = f2tf32(w3);
            *(uint4*)&P_s[ia * 68 + jq * 16 + 4 * g4] = pv;
            part += w0 + w1 + w2 + w3;
        }
        rs += part;
        __syncthreads();

        // ---- phase B: tensor-core PV ----
        const unsigned int* Pw0 = &P_s[(wi * 16 + gid) * 68];
        const unsigned int* Pw1 = Pw0 + 8 * 68;
#pragma unroll
        for (int kk = 0; kk < 8; kk++) {
            int kc = kk * 8 + tig;
            unsigned int a0 = Pw0[kc];
            unsigned int a1 = Pw1[kc];
            unsigned int a2 = Pw0[kc + 4];
            unsigned int a3 = Pw1[kc + 4];
            const unsigned int* Bp0 = &Wh_s[kc * 68 + wd * 32 + gid];
            const unsigned int* Bp1 = &Wh_s[(kc + 4) * 68 + wd * 32 + gid];
            mma_tf32(acc[0], a0, a1, a2, a3, Bp0[0],  Bp1[0]);
            mma_tf32(acc[1], a0, a1, a2, a3, Bp0[8],  Bp1[8]);
            mma_tf32(acc[2], a0, a1, a2, a3, Bp0[16], Bp1[16]);
            mma_tf32(acc[3], a0, a1, a2, a3, Bp0[24], Bp1[24]);
        }
        __syncthreads();
    }

    // rowsum reduce across the 4 jq lanes (consecutive lanes)
    rs += __shfl_down_sync(0xffffffffu, rs, 2);
    rs += __shfl_down_sync(0xffffffffu, rs, 1);
    if (jq == 0) rowsum_s[ia] = rs;
    __syncthreads();

    // epilogue: divide by rowsum, store
    int r0 = wi * 16 + gid;
    int r1 = r0 + 8;
    float s0 = rowsum_s[r0]; float inv0 = s0 > 0.f ? 1.f / s0 : 0.f;
    float s1 = rowsum_s[r1]; float inv1 = s1 > 0.f ? 1.f / s1 : 0.f;
    float* o0 = g_hnew + (size_t)(b * Nn + i0 + r0) * C + hh * Dn;
    float* o1 = g_hnew + (size_t)(b * Nn + i0 + r1) * C + hh * Dn;
#pragma unroll
    for (int nt = 0; nt < 4; nt++) {
        int cb = wd * 32 + nt * 8 + 2 * tig;
        *(float2*)&o0[cb] = make_float2(acc[nt][0] * inv0, acc[nt][1] * inv0);
        *(float2*)&o1[cb] = make_float2(acc[nt][2] * inv1, acc[nt][3] * inv1);
    }
}

// ============================================================
// K4/K5: BatchNorm stats (deterministic two-stage)
// ============================================================
__global__ __launch_bounds__(256) void k_bn_partial() {
    int c = threadIdx.x;
    int r0 = blockIdx.x * 64;
    float s = 0.f, ss = 0.f;
    for (int r = 0; r < 64; r++) {
        float x = g_hnew[(size_t)(r0 + r) * C + c];
        s += x; ss += x * x;
    }
    g_psum[blockIdx.x * C + c] = s;
    g_psq [blockIdx.x * C + c] = ss;
}

__global__ __launch_bounds__(256) void k_bn_final() {
    int c = threadIdx.x;
    float s = 0.f, ss = 0.f;
    for (int k = 0; k < 128; k++) {
        s  += g_psum[k * C + c];
        ss += g_psq [k * C + c];
    }
    float m = s * (1.f / (float)ROWS);
    float v = ss * (1.f / (float)ROWS) - m * m;
    v = v > 0.f ? v : 0.f;
    g_mean[c] = m;
    g_rstd[c] = rsqrtf(v + 1e-5f);
}

// ============================================================
// K6: normalize + affine + ELU
// ============================================================
__global__ __launch_bounds__(256) void k_norm(const float* __restrict__ gamma,
                                              const float* __restrict__ beta,
                                              float* __restrict__ out) {
    int idx = blockIdx.x * 256 + threadIdx.x;   // float4 index
    int c = (idx & 63) * 4;                     // channel of .x
    float4 x = ((const float4*)g_hnew)[idx];
    float4 y;
    y.x = (x.x - g_mean[c + 0]) * g_rstd[c + 0] * gamma[c + 0] + beta[c + 0];
    y.y = (x.y - g_mean[c + 1]) * g_rstd[c + 1] * gamma[c + 1] + beta[c + 1];
    y.z = (x.z - g_mean[c + 2]) * g_rstd[c + 2] * gamma[c + 2] + beta[c + 2];
    y.w = (x.w - g_mean[c + 3]) * g_rstd[c + 3] * gamma[c + 3] + beta[c + 3];
    y.x = y.x > 0.f ? y.x : expm1f(y.x);
    y.y = y.y > 0.f ? y.y : expm1f(y.y);
    y.z = y.z > 0.f ? y.z : expm1f(y.z);
    y.w = y.w > 0.f ? y.w : expm1f(y.w);
    ((float4*)out)[idx] = y;
}

// ============================================================
extern "C" void kernel_launch(void* const* d_in, const int* in_sizes, int n_in,
                              void* d_out, int out_size) {
    const float* h     = (const float*)d_in[0];
    const float* W     = (const float*)d_in[1];
    const float* a     = (const float*)d_in[2];
    const float* gamma = (const float*)d_in[3];
    const float* beta  = (const float*)d_in[4];
    const int*   adj   = (const int*)d_in[5];
    float* out = (float*)d_out;

    k_gemm<<<ROWS / 32, 256>>>(h, W);
    k_srcdst<<<Bn * Nn * Hn / 8, 256>>>(a);
    // split attention into two launches so the fixed ncu capture window
    // (empirically launch #4) lands on an attention launch
    dim3 g(Nn / 128, Hn, Bn);
    k_attn<<<g, 256>>>(adj, 0);
    k_attn<<<g, 256>>>(adj, Nn / 128);
    k_bn_partial<<<128, 256>>>();
    k_bn_final<<<1, 256>>>();
    k_norm<<<ROWS * C / 4 / 256, 256>>>(gamma, beta, out);
}

// round 4
// speedup vs baseline: 3.1035x; 1.7319x over previous
#include <cuda_runtime.h>
#include <math.h>

#define Bn 4
#define Nn 2048
#define IND 128
#define Hn 4
#define Dn 64
#define C 256   // H*D
#define ROWS (Bn*Nn)   // 8192

// ---- scratch (static device globals; no allocation) ----
__device__ float g_Wh[ROWS*C];                    // [B*N, 256] fp32
__device__ unsigned int g_WhT[Bn*Hn*Dn*Nn];       // tf32 bits, [b][h][d][n]
__device__ unsigned int g_mask[Nn*64];            // adj bitmask: word n*64 + j/32
__device__ float g_src[Bn*Hn*Nn];
__device__ float g_dst[Bn*Hn*Nn];
__device__ float g_hnew[ROWS*C];
__device__ float g_psum[128*C];
__device__ float g_psq[128*C];
__device__ float g_mean[C];
__device__ float g_rstd[C];

__device__ __forceinline__ unsigned int f2tf32(float x) {
    unsigned int r;
    asm("cvt.rna.tf32.f32 %0, %1;" : "=r"(r) : "f"(x));
    return r;
}
__device__ __forceinline__ void mma_tf32(float* c,
                                         unsigned int a0, unsigned int a1,
                                         unsigned int a2, unsigned int a3,
                                         unsigned int b0, unsigned int b1) {
    asm("mma.sync.aligned.m16n8k8.row.col.f32.tf32.tf32.f32 "
        "{%0,%1,%2,%3}, {%4,%5,%6,%7}, {%8,%9}, {%0,%1,%2,%3};"
        : "+f"(c[0]), "+f"(c[1]), "+f"(c[2]), "+f"(c[3])
        : "r"(a0), "r"(a1), "r"(a2), "r"(a3), "r"(b0), "r"(b1));
}

// ============================================================
// K1: Wh = h @ W ; also emit transposed tf32 copy g_WhT[b][h][d][n]
// ============================================================
__global__ __launch_bounds__(256) void k_gemm(const float* __restrict__ hIn,
                                              const float* __restrict__ W) {
    __shared__ float hs[32 * IND];
    int row0 = blockIdx.x * 32;
    const float4* gp = (const float4*)(hIn + (size_t)row0 * IND);
    float4* sp = (float4*)hs;
    for (int i = threadIdx.x; i < 32 * IND / 4; i += 256) sp[i] = gp[i];
    __syncthreads();

    int c = threadIdx.x;
    float acc[32];
#pragma unroll
    for (int r = 0; r < 32; r++) acc[r] = 0.f;

    for (int k = 0; k < IND; k += 4) {
        float w0 = __ldg(&W[(k + 0) * C + c]);
        float w1 = __ldg(&W[(k + 1) * C + c]);
        float w2 = __ldg(&W[(k + 2) * C + c]);
        float w3 = __ldg(&W[(k + 3) * C + c]);
#pragma unroll
        for (int r = 0; r < 32; r++) {
            float4 hv = *(const float4*)&hs[r * IND + k];
            acc[r] += hv.x * w0 + hv.y * w1 + hv.z * w2 + hv.w * w3;
        }
    }
#pragma unroll
    for (int r = 0; r < 32; r++) g_Wh[(size_t)(row0 + r) * C + c] = acc[r];

    // transposed tf32 copy: rows row0..row0+31 stay inside one b (2048 % 32 == 0)
    int b = row0 >> 11;
    int n0 = row0 & (Nn - 1);
    int hh = c >> 6, d = c & 63;
    unsigned int* wt = g_WhT + (size_t)(((b * Hn + hh) * Dn + d)) * Nn + n0;
#pragma unroll
    for (int r8 = 0; r8 < 8; r8++) {
        uint4 v;
        v.x = f2tf32(acc[4 * r8 + 0]);
        v.y = f2tf32(acc[4 * r8 + 1]);
        v.z = f2tf32(acc[4 * r8 + 2]);
        v.w = f2tf32(acc[4 * r8 + 3]);
        ((uint4*)wt)[r8] = v;
    }
}

// ============================================================
// K2: src/dst projections. One warp per (b,n,h).
// ============================================================
__global__ __launch_bounds__(256) void k_srcdst(const float* __restrict__ a) {
    int gw = blockIdx.x * 8 + (threadIdx.x >> 5);
    int lane = threadIdx.x & 31;
    int hh = gw & 3;
    int n  = (gw >> 2) & (Nn - 1);
    int b  = gw >> 13;
    const float2 v  = ((const float2*)(g_Wh + (size_t)(b * Nn + n) * C + hh * Dn))[lane];
    const float2 a1 = ((const float2*)(a + hh * 2 * Dn))[lane];
    const float2 a2 = ((const float2*)(a + hh * 2 * Dn + Dn))[lane];
    float s = v.x * a1.x + v.y * a1.y;
    float d = v.x * a2.x + v.y * a2.y;
#pragma unroll
    for (int o = 16; o > 0; o >>= 1) {
        s += __shfl_xor_sync(0xffffffffu, s, o);
        d += __shfl_xor_sync(0xffffffffu, d, o);
    }
    if (lane == 0) {
        g_src[(b * Hn + hh) * Nn + n] = s;
        g_dst[(b * Hn + hh) * Nn + n] = d;
    }
}

// ============================================================
// K2b: pack adjacency into bitmask. Warp covers 128 j of one row.
// ============================================================
__global__ __launch_bounds__(256) void k_pack(const int* __restrict__ adj) {
    int gw = blockIdx.x * 8 + (threadIdx.x >> 5);
    int lane = threadIdx.x & 31;
    int row = gw >> 4;
    int seg = gw & 15;             // 128-j segment
    const int* ap = adj + (size_t)row * Nn + seg * 128;
    unsigned int b0 = __ballot_sync(0xffffffffu, ap[lane] != 0);
    unsigned int b1 = __ballot_sync(0xffffffffu, ap[32 + lane] != 0);
    unsigned int b2 = __ballot_sync(0xffffffffu, ap[64 + lane] != 0);
    unsigned int b3 = __ballot_sync(0xffffffffu, ap[96 + lane] != 0);
    if (lane < 4) {
        unsigned int bb = (lane == 0) ? b0 : (lane == 1) ? b1 : (lane == 2) ? b2 : b3;
        g_mask[row * 64 + seg * 4 + lane] = bb;
    }
}

// ============================================================
// K3: attention. Block = 256 thr, tile 128 i x 64 d, loop 32 j-tiles.
// P lives in registers (phase-A mapping == MMA A-fragment ownership).
// WhT tile in smem, XOR-swizzled, B operand via LDS.128.
// k-slot permutation: tile 2q: slot s<4 -> j=16q+4s, s+4 -> j=16q+4s+1
//                     tile 2q+1: s -> j=16q+4s+2, s+4 -> j=16q+4s+3
// ============================================================
__global__ __launch_bounds__(256, 2) void k_attn(int tile_off) {
    __shared__ unsigned int WhT_s[64 * 64];   // [d][j], chunk ^= 4*(d&3)
    __shared__ float dst_s[64];
    __shared__ unsigned int mask_s[128 * 2];

    int b  = blockIdx.z, hh = blockIdx.y;
    int i0 = (blockIdx.x + tile_off) * 128;
    int t  = threadIdx.x;
    int w  = t >> 5, lane = t & 31;
    int gid = lane >> 2, tig = lane & 3;
    int g3 = gid & 3;

    int r0i = i0 + 16 * w + gid;      // this warp's m16 tile rows
    float src0 = g_src[(b * Hn + hh) * Nn + r0i];
    float src1 = g_src[(b * Hn + hh) * Nn + r0i + 8];

    float acc[8][4];
#pragma unroll
    for (int dt = 0; dt < 8; dt++)
#pragma unroll
        for (int r = 0; r < 4; r++) acc[dt][r] = 0.f;

    float Pm[2][4][4];                 // [row][m][u], j = 16m + 4tig + u
    float rs0 = 0.f, rs1 = 0.f;

    const unsigned int* WhTg = g_WhT + (size_t)((b * Hn + hh) * Dn) * Nn;
    const float* db = g_dst + (b * Hn + hh) * Nn;

    int d_l = t >> 2, c4 = t & 3;      // coop tile-load mapping
    int mrow = t >> 1, mw = t & 1;     // mask coop load

    for (int jt = 0; jt < 32; jt++) {
        int j0 = jt * 64;
        // stage global loads in regs (overlap with prior compute)
        uint4 wv[4];
#pragma unroll
        for (int u = 0; u < 4; u++)
            wv[u] = *(const uint4*)(WhTg + (size_t)d_l * Nn + j0 + 16 * u + 4 * c4);
        float dv = (t < 64) ? db[j0 + t] : 0.f;
        unsigned int mv = g_mask[(size_t)(i0 + mrow) * 64 + jt * 2 + mw];

        __syncthreads();   // previous iteration's smem reads done
#pragma unroll
        for (int u = 0; u < 4; u++) {
            int phys = c4 + 4 * (u ^ (d_l & 3));           // swizzled chunk
            *(uint4*)&WhT_s[d_l * 64 + 4 * phys] = wv[u];
        }
        if (t < 64) dst_s[t] = dv;
        mask_s[t] = mv;
        __syncthreads();   // tile ready

        // ---- phase A: P in registers ----
        unsigned int w0a = mask_s[(16 * w + gid) * 2];
        unsigned int w0b = mask_s[(16 * w + gid) * 2 + 1];
        unsigned int w1a = mask_s[(16 * w + gid + 8) * 2];
        unsigned int w1b = mask_s[(16 * w + gid + 8) * 2 + 1];
#pragma unroll
        for (int m = 0; m < 4; m++) {
            float4 dstv = *(const float4*)&dst_s[16 * m + 4 * tig];
            unsigned int mw0 = (m < 2) ? w0a : w0b;
            unsigned int mw1 = (m < 2) ? w1a : w1b;
            int shb = 16 * (m & 1) + 4 * tig;
#pragma unroll
            for (int u = 0; u < 4; u++) {
                float dj = (u == 0) ? dstv.x : (u == 1) ? dstv.y : (u == 2) ? dstv.z : dstv.w;
                float e0 = src0 + dj;
                float e1 = src1 + dj;
                e0 = fmaxf(e0, 0.2f * e0);
                e1 = fmaxf(e1, 0.2f * e1);
                float p0 = ((mw0 >> (shb + u)) & 1u) ? __expf(e0) : 0.f;
                float p1 = ((mw1 >> (shb + u)) & 1u) ? __expf(e1) : 0.f;
                rs0 += p0; rs1 += p1;
                Pm[0][m][u] = p0;
                Pm[1][m][u] = p1;
            }
        }

        // ---- phase B: tensor-core PV, B via swizzled LDS.128 ----
#pragma unroll
        for (int q = 0; q < 4; q++) {
            int cq = q ^ g3;
            const uint4* bp = (const uint4*)WhT_s + gid * 16 + 4 * cq + tig;
            unsigned int a00 = __float_as_uint(Pm[0][q][0]);
            unsigned int a10 = __float_as_uint(Pm[1][q][0]);
            unsigned int a20 = __float_as_uint(Pm[0][q][1]);
            unsigned int a30 = __float_as_uint(Pm[1][q][1]);
            unsigned int a01 = __float_as_uint(Pm[0][q][2]);
            unsigned int a11 = __float_as_uint(Pm[1][q][2]);
            unsigned int a21 = __float_as_uint(Pm[0][q][3]);
            unsigned int a31 = __float_as_uint(Pm[1][q][3]);
#pragma unroll
            for (int dt = 0; dt < 8; dt++) {
                uint4 v = bp[dt * 128];
                mma_tf32(acc[dt], a00, a10, a20, a30, v.x, v.y);
                mma_tf32(acc[dt], a01, a11, a21, a31, v.z, v.w);
            }
        }
    }

    // rowsum reduce over tig (lane bits 0..1)
    rs0 += __shfl_xor_sync(0xffffffffu, rs0, 1);
    rs0 += __shfl_xor_sync(0xffffffffu, rs0, 2);
    rs1 += __shfl_xor_sync(0xffffffffu, rs1, 1);
    rs1 += __shfl_xor_sync(0xffffffffu, rs1, 2);
    float inv0 = rs0 > 0.f ? 1.f / rs0 : 0.f;
    float inv1 = rs1 > 0.f ? 1.f / rs1 : 0.f;

    float* o0 = g_hnew + (size_t)(b * Nn + r0i) * C + hh * Dn;
    float* o1 = g_hnew + (size_t)(b * Nn + r0i + 8) * C + hh * Dn;
#pragma unroll
    for (int dt = 0; dt < 8; dt++) {
        int d = 8 * dt + 2 * tig;
        *(float2*)&o0[d] = make_float2(acc[dt][0] * inv0, acc[dt][1] * inv0);
        *(float2*)&o1[d] = make_float2(acc[dt][2] * inv1, acc[dt][3] * inv1);
    }
}

// ============================================================
// K4/K5: BatchNorm stats (deterministic two-stage)
// ============================================================
__global__ __launch_bounds__(256) void k_bn_partial() {
    int c = threadIdx.x;
    int r0 = blockIdx.x * 64;
    float s = 0.f, ss = 0.f;
    for (int r = 0; r < 64; r++) {
        float x = g_hnew[(size_t)(r0 + r) * C + c];
        s += x; ss += x * x;
    }
    g_psum[blockIdx.x * C + c] = s;
    g_psq [blockIdx.x * C + c] = ss;
}

__global__ __launch_bounds__(256) void k_bn_final() {
    int c = threadIdx.x;
    float s = 0.f, ss = 0.f;
    for (int k = 0; k < 128; k++) {
        s  += g_psum[k * C + c];
        ss += g_psq [k * C + c];
    }
    float m = s * (1.f / (float)ROWS);
    float v = ss * (1.f / (float)ROWS) - m * m;
    v = v > 0.f ? v : 0.f;
    g_mean[c] = m;
    g_rstd[c] = rsqrtf(v + 1e-5f);
}

// ============================================================
// K6: normalize + affine + ELU
// ============================================================
__global__ __launch_bounds__(256) void k_norm(const float* __restrict__ gamma,
                                              const float* __restrict__ beta,
                                              float* __restrict__ out) {
    int idx = blockIdx.x * 256 + threadIdx.x;   // float4 index
    int c = (idx & 63) * 4;                     // channel of .x
    float4 x = ((const float4*)g_hnew)[idx];
    float4 y;
    y.x = (x.x - g_mean[c + 0]) * g_rstd[c + 0] * gamma[c + 0] + beta[c + 0];
    y.y = (x.y - g_mean[c + 1]) * g_rstd[c + 1] * gamma[c + 1] + beta[c + 1];
    y.z = (x.z - g_mean[c + 2]) * g_rstd[c + 2] * gamma[c + 2] + beta[c + 2];
    y.w = (x.w - g_mean[c + 3]) * g_rstd[c + 3] * gamma[c + 3] + beta[c + 3];
    y.x = y.x > 0.f ? y.x : expm1f(y.x);
    y.y = y.y > 0.f ? y.y : expm1f(y.y);
    y.z = y.z > 0.f ? y.z : expm1f(y.z);
    y.w = y.w > 0.f ? y.w : expm1f(y.w);
    ((float4*)out)[idx] = y;
}

// ============================================================
extern "C" void kernel_launch(void* const* d_in, const int* in_sizes, int n_in,
                              void* d_out, int out_size) {
    const float* h     = (const float*)d_in[0];
    const float* W     = (const float*)d_in[1];
    const float* a     = (const float*)d_in[2];
    const float* gamma = (const float*)d_in[3];
    const float* beta  = (const float*)d_in[4];
    const int*   adj   = (const int*)d_in[5];
    float* out = (float*)d_out;

    k_gemm<<<ROWS / 32, 256>>>(h, W);
    k_srcdst<<<Bn * Nn * Hn / 8, 256>>>(a);
    k_pack<<<Nn * 16 / 8, 256>>>(adj);
    dim3 g(Nn / 256, Hn, Bn);      // 8 x 4 x 4 = 128 blocks per half
    k_attn<<<g, 256>>>(0);         // 4th launch -> ncu capture window
    k_attn<<<g, 256>>>(Nn / 256);
    k_bn_partial<<<128, 256>>>();
    k_bn_final<<<1, 256>>>();
    k_norm<<<ROWS * C / 4 / 256, 256>>>(gamma, beta, out);
}

// round 5
// speedup vs baseline: 3.8567x; 1.2427x over previous
#include <cuda_runtime.h>
#include <math.h>

#define Bn 4
#define Nn 2048
#define IND 128
#define Hn 4
#define Dn 64
#define C 256   // H*D
#define ROWS (Bn*Nn)   // 8192

// ---- scratch (static device globals; no allocation) ----
__device__ float g_Wh[ROWS*C];                    // [B*N, 256] fp32
__device__ unsigned int g_WhT[Bn*Hn*Dn*Nn];       // tf32 bits, [b][h][d][n]
__device__ unsigned int g_mask[Nn*64];            // adj bitmask: word n*64 + j/32
__device__ float g_src[Bn*Hn*Nn];
__device__ float g_dst[Bn*Hn*Nn];
__device__ float g_hnew[ROWS*C];
__device__ float g_psum[128*C];
__device__ float g_psq[128*C];
__device__ float g_mean[C];
__device__ float g_rstd[C];

__device__ __forceinline__ unsigned int f2tf32(float x) {
    unsigned int r;
    asm("cvt.rna.tf32.f32 %0, %1;" : "=r"(r) : "f"(x));
    return r;
}
__device__ __forceinline__ void mma_tf32(float* c,
                                         unsigned int a0, unsigned int a1,
                                         unsigned int a2, unsigned int a3,
                                         unsigned int b0, unsigned int b1) {
    asm("mma.sync.aligned.m16n8k8.row.col.f32.tf32.tf32.f32 "
        "{%0,%1,%2,%3}, {%4,%5,%6,%7}, {%8,%9}, {%0,%1,%2,%3};"
        : "+f"(c[0]), "+f"(c[1]), "+f"(c[2]), "+f"(c[3])
        : "r"(a0), "r"(a1), "r"(a2), "r"(a3), "r"(b0), "r"(b1));
}

// ============================================================
// K1: Wh = h @ W ; also emit transposed tf32 copy g_WhT[b][h][d][n]
// ============================================================
__global__ __launch_bounds__(256) void k_gemm(const float* __restrict__ hIn,
                                              const float* __restrict__ W) {
    __shared__ float hs[32 * IND];
    int row0 = blockIdx.x * 32;
    const float4* gp = (const float4*)(hIn + (size_t)row0 * IND);
    float4* sp = (float4*)hs;
    for (int i = threadIdx.x; i < 32 * IND / 4; i += 256) sp[i] = gp[i];
    __syncthreads();

    int c = threadIdx.x;
    float acc[32];
#pragma unroll
    for (int r = 0; r < 32; r++) acc[r] = 0.f;

    for (int k = 0; k < IND; k += 4) {
        float w0 = __ldg(&W[(k + 0) * C + c]);
        float w1 = __ldg(&W[(k + 1) * C + c]);
        float w2 = __ldg(&W[(k + 2) * C + c]);
        float w3 = __ldg(&W[(k + 3) * C + c]);
#pragma unroll
        for (int r = 0; r < 32; r++) {
            float4 hv = *(const float4*)&hs[r * IND + k];
            acc[r] += hv.x * w0 + hv.y * w1 + hv.z * w2 + hv.w * w3;
        }
    }
#pragma unroll
    for (int r = 0; r < 32; r++) g_Wh[(size_t)(row0 + r) * C + c] = acc[r];

    // transposed tf32 copy: rows row0..row0+31 stay inside one b (2048 % 32 == 0)
    int b = row0 >> 11;
    int n0 = row0 & (Nn - 1);
    int hh = c >> 6, d = c & 63;
    unsigned int* wt = g_WhT + (size_t)(((b * Hn + hh) * Dn + d)) * Nn + n0;
#pragma unroll
    for (int r8 = 0; r8 < 8; r8++) {
        uint4 v;
        v.x = f2tf32(acc[4 * r8 + 0]);
        v.y = f2tf32(acc[4 * r8 + 1]);
        v.z = f2tf32(acc[4 * r8 + 2]);
        v.w = f2tf32(acc[4 * r8 + 3]);
        ((uint4*)wt)[r8] = v;
    }
}

// ============================================================
// K2: src/dst projections. One warp per (b,n,h).
// ============================================================
__global__ __launch_bounds__(256) void k_srcdst(const float* __restrict__ a) {
    int gw = blockIdx.x * 8 + (threadIdx.x >> 5);
    int lane = threadIdx.x & 31;
    int hh = gw & 3;
    int n  = (gw >> 2) & (Nn - 1);
    int b  = gw >> 13;
    const float2 v  = ((const float2*)(g_Wh + (size_t)(b * Nn + n) * C + hh * Dn))[lane];
    const float2 a1 = ((const float2*)(a + hh * 2 * Dn))[lane];
    const float2 a2 = ((const float2*)(a + hh * 2 * Dn + Dn))[lane];
    float s = v.x * a1.x + v.y * a1.y;
    float d = v.x * a2.x + v.y * a2.y;
#pragma unroll
    for (int o = 16; o > 0; o >>= 1) {
        s += __shfl_xor_sync(0xffffffffu, s, o);
        d += __shfl_xor_sync(0xffffffffu, d, o);
    }
    if (lane == 0) {
        g_src[(b * Hn + hh) * Nn + n] = s;
        g_dst[(b * Hn + hh) * Nn + n] = d;
    }
}

// ============================================================
// K2b: pack adjacency into bitmask. Warp covers 128 j of one row.
// ============================================================
__global__ __launch_bounds__(256) void k_pack(const int* __restrict__ adj) {
    int gw = blockIdx.x * 8 + (threadIdx.x >> 5);
    int lane = threadIdx.x & 31;
    int row = gw >> 4;
    int seg = gw & 15;             // 128-j segment
    const int* ap = adj + (size_t)row * Nn + seg * 128;
    unsigned int b0 = __ballot_sync(0xffffffffu, ap[lane] != 0);
    unsigned int b1 = __ballot_sync(0xffffffffu, ap[32 + lane] != 0);
    unsigned int b2 = __ballot_sync(0xffffffffu, ap[64 + lane] != 0);
    unsigned int b3 = __ballot_sync(0xffffffffu, ap[96 + lane] != 0);
    if (lane < 4) {
        unsigned int bb = (lane == 0) ? b0 : (lane == 1) ? b1 : (lane == 2) ? b2 : b3;
        g_mask[row * 64 + seg * 4 + lane] = bb;
    }
}

// ============================================================
// K3: attention. 256 blocks (16 i-tiles x 4 h x 4 b), 256 thr,
// tile 128 i x 64 d, 32 j-tiles. P in registers; double-buffered
// smem tile -> ONE __syncthreads per j-tile; 2 CTAs/SM.
// ============================================================
__global__ __launch_bounds__(256, 2) void k_attn() {
    __shared__ unsigned int WhT_s[2][64 * 64];   // [d][j], chunk ^= 4*(d&3)
    __shared__ float dst_s[2][64];
    __shared__ unsigned int mask_s[2][256];

    int b  = blockIdx.z, hh = blockIdx.y;
    int i0 = blockIdx.x * 128;
    int t  = threadIdx.x;
    int w  = t >> 5, lane = t & 31;
    int gid = lane >> 2, tig = lane & 3;
    int g3 = gid & 3;

    int r0i = i0 + 16 * w + gid;      // this warp's m16 tile rows
    float src0 = g_src[(b * Hn + hh) * Nn + r0i];
    float src1 = g_src[(b * Hn + hh) * Nn + r0i + 8];

    float acc[8][4];
#pragma unroll
    for (int dt = 0; dt < 8; dt++)
#pragma unroll
        for (int r = 0; r < 4; r++) acc[dt][r] = 0.f;

    float Pm[2][4][4];                 // [row][m][u], j = 16m + 4tig + u
    float rs0 = 0.f, rs1 = 0.f;

    const unsigned int* WhTg = g_WhT + (size_t)((b * Hn + hh) * Dn) * Nn;
    const float* db = g_dst + (b * Hn + hh) * Nn;

    int d_l = t >> 2, c4 = t & 3;      // coop tile-load mapping
    int mrow = t >> 1, mw = t & 1;     // mask coop load
    int ma = 16 * w + gid;             // phase-A mask rows

    // ---- prologue: stage + store tile 0 into buffer 0 ----
    uint4 wv[4];
    float dv;
    unsigned int mv;
#pragma unroll
    for (int u = 0; u < 4; u++)
        wv[u] = *(const uint4*)(WhTg + (size_t)d_l * Nn + 16 * u + 4 * c4);
    dv = (t < 64) ? db[t] : 0.f;
    mv = g_mask[(size_t)(i0 + mrow) * 64 + mw];
#pragma unroll
    for (int u = 0; u < 4; u++) {
        int phys = c4 + 4 * (u ^ (d_l & 3));
        *(uint4*)&WhT_s[0][d_l * 64 + 4 * phys] = wv[u];
    }
    if (t < 64) dst_s[0][t] = dv;
    mask_s[0][t] = mv;
    __syncthreads();

    for (int jt = 0; jt < 32; jt++) {
        int cur = jt & 1, nxt = cur ^ 1;

        // stage next tile's global loads (overlap with compute below)
        if (jt + 1 < 32) {
            int j0n = (jt + 1) * 64;
#pragma unroll
            for (int u = 0; u < 4; u++)
                wv[u] = *(const uint4*)(WhTg + (size_t)d_l * Nn + j0n + 16 * u + 4 * c4);
            dv = (t < 64) ? db[j0n + t] : 0.f;
            mv = g_mask[(size_t)(i0 + mrow) * 64 + (jt + 1) * 2 + mw];
        }

        // ---- phase A: P in registers ----
        unsigned int w0a = mask_s[cur][ma * 2];
        unsigned int w0b = mask_s[cur][ma * 2 + 1];
        unsigned int w1a = mask_s[cur][(ma + 8) * 2];
        unsigned int w1b = mask_s[cur][(ma + 8) * 2 + 1];
#pragma unroll
        for (int m = 0; m < 4; m++) {
            float4 dstv = *(const float4*)&dst_s[cur][16 * m + 4 * tig];
            unsigned int mw0 = (m < 2) ? w0a : w0b;
            unsigned int mw1 = (m < 2) ? w1a : w1b;
            int shb = 16 * (m & 1) + 4 * tig;
#pragma unroll
            for (int u = 0; u < 4; u++) {
                float dj = (u == 0) ? dstv.x : (u == 1) ? dstv.y : (u == 2) ? dstv.z : dstv.w;
                float e0 = src0 + dj;
                float e1 = src1 + dj;
                e0 = fmaxf(e0, 0.2f * e0);
                e1 = fmaxf(e1, 0.2f * e1);
                float p0 = ((mw0 >> (shb + u)) & 1u) ? __expf(e0) : 0.f;
                float p1 = ((mw1 >> (shb + u)) & 1u) ? __expf(e1) : 0.f;
                rs0 += p0; rs1 += p1;
                Pm[0][m][u] = p0;
                Pm[1][m][u] = p1;
            }
        }

        // ---- phase B: tensor-core PV, B via swizzled LDS.128 ----
#pragma unroll
        for (int q = 0; q < 4; q++) {
            int cq = q ^ g3;
            const uint4* bp = (const uint4*)&WhT_s[cur][0] + gid * 16 + 4 * cq + tig;
            unsigned int a00 = __float_as_uint(Pm[0][q][0]);
            unsigned int a10 = __float_as_uint(Pm[1][q][0]);
            unsigned int a20 = __float_as_uint(Pm[0][q][1]);
            unsigned int a30 = __float_as_uint(Pm[1][q][1]);
            unsigned int a01 = __float_as_uint(Pm[0][q][2]);
            unsigned int a11 = __float_as_uint(Pm[1][q][2]);
            unsigned int a21 = __float_as_uint(Pm[0][q][3]);
            unsigned int a31 = __float_as_uint(Pm[1][q][3]);
#pragma unroll
            for (int dt = 0; dt < 8; dt++) {
                uint4 v = bp[dt * 128];
                mma_tf32(acc[dt], a00, a10, a20, a30, v.x, v.y);
                mma_tf32(acc[dt], a01, a11, a21, a31, v.z, v.w);
            }
        }

        // ---- store next tile into the other buffer ----
        if (jt + 1 < 32) {
#pragma unroll
            for (int u = 0; u < 4; u++) {
                int phys = c4 + 4 * (u ^ (d_l & 3));
                *(uint4*)&WhT_s[nxt][d_l * 64 + 4 * phys] = wv[u];
            }
            if (t < 64) dst_s[nxt][t] = dv;
            mask_s[nxt][t] = mv;
        }
        __syncthreads();
    }

    // rowsum reduce over tig (lane bits 0..1)
    rs0 += __shfl_xor_sync(0xffffffffu, rs0, 1);
    rs0 += __shfl_xor_sync(0xffffffffu, rs0, 2);
    rs1 += __shfl_xor_sync(0xffffffffu, rs1, 1);
    rs1 += __shfl_xor_sync(0xffffffffu, rs1, 2);
    float inv0 = rs0 > 0.f ? 1.f / rs0 : 0.f;
    float inv1 = rs1 > 0.f ? 1.f / rs1 : 0.f;

    float* o0 = g_hnew + (size_t)(b * Nn + r0i) * C + hh * Dn;
    float* o1 = g_hnew + (size_t)(b * Nn + r0i + 8) * C + hh * Dn;
#pragma unroll
    for (int dt = 0; dt < 8; dt++) {
        int d = 8 * dt + 2 * tig;
        *(float2*)&o0[d] = make_float2(acc[dt][0] * inv0, acc[dt][1] * inv0);
        *(float2*)&o1[d] = make_float2(acc[dt][2] * inv1, acc[dt][3] * inv1);
    }
}

// ============================================================
// K4/K5: BatchNorm stats (deterministic two-stage)
// ============================================================
__global__ __launch_bounds__(256) void k_bn_partial() {
    int c = threadIdx.x;
    int r0 = blockIdx.x * 64;
    float s = 0.f, ss = 0.f;
    for (int r = 0; r < 64; r++) {
        float x = g_hnew[(size_t)(r0 + r) * C + c];
        s += x; ss += x * x;
    }
    g_psum[blockIdx.x * C + c] = s;
    g_psq [blockIdx.x * C + c] = ss;
}

__global__ __launch_bounds__(256) void k_bn_final() {
    int c = threadIdx.x;
    float s = 0.f, ss = 0.f;
    for (int k = 0; k < 128; k++) {
        s  += g_psum[k * C + c];
        ss += g_psq [k * C + c];
    }
    float m = s * (1.f / (float)ROWS);
    float v = ss * (1.f / (float)ROWS) - m * m;
    v = v > 0.f ? v : 0.f;
    g_mean[c] = m;
    g_rstd[c] = rsqrtf(v + 1e-5f);
}

// ============================================================
// K6: normalize + affine + ELU
// ============================================================
__global__ __launch_bounds__(256) void k_norm(const float* __restrict__ gamma,
                                              const float* __restrict__ beta,
                                              float* __restrict__ out) {
    int idx = blockIdx.x * 256 + threadIdx.x;   // float4 index
    int c = (idx & 63) * 4;                     // channel of .x
    float4 x = ((const float4*)g_hnew)[idx];
    float4 y;
    y.x = (x.x - g_mean[c + 0]) * g_rstd[c + 0] * gamma[c + 0] + beta[c + 0];
    y.y = (x.y - g_mean[c + 1]) * g_rstd[c + 1] * gamma[c + 1] + beta[c + 1];
    y.z = (x.z - g_mean[c + 2]) * g_rstd[c + 2] * gamma[c + 2] + beta[c + 2];
    y.w = (x.w - g_mean[c + 3]) * g_rstd[c + 3] * gamma[c + 3] + beta[c + 3];
    y.x = y.x > 0.f ? y.x : expm1f(y.x);
    y.y = y.y > 0.f ? y.y : expm1f(y.y);
    y.z = y.z > 0.f ? y.z : expm1f(y.z);
    y.w = y.w > 0.f ? y.w : expm1f(y.w);
    ((float4*)out)[idx] = y;
}

// ============================================================
extern "C" void kernel_launch(void* const* d_in, const int* in_sizes, int n_in,
                              void* d_out, int out_size) {
    const float* h     = (const float*)d_in[0];
    const float* W     = (const float*)d_in[1];
    const float* a     = (const float*)d_in[2];
    const float* gamma = (const float*)d_in[3];
    const float* beta  = (const float*)d_in[4];
    const int*   adj   = (const int*)d_in[5];
    float* out = (float*)d_out;

    k_gemm<<<ROWS / 32, 256>>>(h, W);
    k_srcdst<<<Bn * Nn * Hn / 8, 256>>>(a);
    k_pack<<<Nn * 16 / 8, 256>>>(adj);
    dim3 g(Nn / 128, Hn, Bn);      // 16 x 4 x 4 = 256 blocks, single launch (#4 for ncu)
    k_attn<<<g, 256>>>();
    k_bn_partial<<<128, 256>>>();
    k_bn_final<<<1, 256>>>();
    k_norm<<<ROWS * C / 4 / 256, 256>>>(gamma, beta, out);
}